// round 7
// baseline (speedup 1.0000x reference)
#include <cuda_runtime.h>
#include <cstdint>

#define BATCH 64
#define TDIM  2048
#define QDIM  512
#define KDIM  512
#define QSPLIT 4
#define QCHUNK (QDIM / QSPLIT)   // 128

// ---- scores pipeline config ----
#define STAGES          6
#define STAGE_ROWS      16
#define STAGE_BYTES     (STAGE_ROWS * KDIM * 4)        // 32768
#define TILE_ROWS       128
#define STAGES_PER_TILE (TILE_ROWS / STAGE_ROWS)       // 8
#define TILES_PER_B     (TDIM / TILE_ROWS)             // 16
#define NTILES          (BATCH * TILES_PER_B)          // 1024
#define CONS_WARPS      8
#define NTHREADS        (CONS_WARPS * 32 + 32)         // 288 (8 consumers + 1 producer warp)
#define SMEM_RING       (STAGES * STAGE_BYTES)
#define SMEM_TOTAL      (SMEM_RING + STAGES * 16)      // + full/empty mbarrier pairs

// Scratch (no allocations allowed in kernel_launch)
__device__ float g_part[QSPLIT][BATCH * KDIM];  // partial mids per q-chunk
__device__ float g_sums[BATCH];

// ---------------- mbarrier helpers ----------------
#define MBARRIER_INIT(addr, count) \
    asm volatile("mbarrier.init.shared.b64 [%0], %1;" :: "r"(addr), "r"(count) : "memory")
#define MBARRIER_EXPECT_TX(addr, bytes) \
    asm volatile("mbarrier.arrive.expect_tx.shared.b64 _, [%0], %1;" :: "r"(addr), "r"(bytes) : "memory")
#define MBARRIER_ARRIVE(addr) \
    asm volatile("mbarrier.arrive.shared.b64 _, [%0];" :: "r"(addr) : "memory")

__device__ __forceinline__ void mbar_wait(uint32_t addr, uint32_t parity) {
    asm volatile(
        "{\n\t"
        ".reg .pred P1;\n\t"
        "WAIT_LOOP_%=:\n\t"
        "mbarrier.try_wait.parity.acquire.cta.shared::cta.b64 P1, [%0], %1, 0x989680;\n\t"
        "@P1 bra.uni WAIT_DONE_%=;\n\t"
        "bra.uni WAIT_LOOP_%=;\n\t"
        "WAIT_DONE_%=:\n\t"
        "}" :: "r"(addr), "r"(parity) : "memory");
}
__device__ __forceinline__ void mbar_wait_relaxed(uint32_t addr, uint32_t parity) {
    asm volatile(
        "{\n\t"
        ".reg .pred P1;\n\t"
        "WAIT_LOOP_%=:\n\t"
        "mbarrier.try_wait.parity.relaxed.cta.shared::cta.b64 P1, [%0], %1, 0x989680;\n\t"
        "@P1 bra.uni WAIT_DONE_%=;\n\t"
        "bra.uni WAIT_LOOP_%=;\n\t"
        "WAIT_DONE_%=:\n\t"
        "}" :: "r"(addr), "r"(parity) : "memory");
}
__device__ __forceinline__ void bulk_load(uint32_t smem_dst, const void* gmem_src,
                                          uint32_t bytes, uint32_t mbar) {
    asm volatile(
        "cp.async.bulk.shared::cta.global.mbarrier::complete_tx::bytes [%0], [%1], %2, [%3];"
        :: "r"(smem_dst), "l"(gmem_src), "r"(bytes), "r"(mbar) : "memory");
}

// ---------------------------------------------------------------------------
// Kernel 1: partial mids (unchanged from R6). grid = 2048, 256 thr.
// ---------------------------------------------------------------------------
__global__ void __launch_bounds__(256)
mids_kernel(const float* __restrict__ query,
            const float* __restrict__ W)
{
    const int qs = blockIdx.x & 3;
    const int kt = (blockIdx.x >> 2) & 31;
    const int bt = blockIdx.x >> 7;

    if (blockIdx.x == 0 && threadIdx.x < BATCH) g_sums[threadIdx.x] = 0.0f;

    __shared__ float q_s[4][QCHUNK];
    for (int i = threadIdx.x; i < 4 * QCHUNK; i += blockDim.x) {
        int bb = i >> 7;
        int q  = i & (QCHUNK - 1);
        q_s[bb][q] = query[(size_t)(bt * 4 + bb) * QDIM + qs * QCHUNK + q];
    }
    __syncthreads();

    const int warp = threadIdx.x >> 5;
    const int lane = threadIdx.x & 31;

    float4 qv[4];
#pragma unroll
    for (int bb = 0; bb < 4; bb++)
        qv[bb] = reinterpret_cast<const float4*>(q_s[bb])[lane];

    const int k0 = kt * 16 + warp * 2;
    const int k1 = k0 + 1;
    const float4 wa = reinterpret_cast<const float4*>(
        W + (size_t)k0 * QDIM + qs * QCHUNK)[lane];
    const float4 wb = reinterpret_cast<const float4*>(
        W + (size_t)k1 * QDIM + qs * QCHUNK)[lane];

    float a[2][4];
#pragma unroll
    for (int bb = 0; bb < 4; bb++) {
        const float4 v = qv[bb];
        a[0][bb] = wa.x * v.x + wa.y * v.y + wa.z * v.z + wa.w * v.w;
        a[1][bb] = wb.x * v.x + wb.y * v.y + wb.z * v.z + wb.w * v.w;
    }
#pragma unroll
    for (int o = 16; o; o >>= 1) {
#pragma unroll
        for (int bb = 0; bb < 4; bb++) {
            a[0][bb] += __shfl_xor_sync(0xffffffffu, a[0][bb], o);
            a[1][bb] += __shfl_xor_sync(0xffffffffu, a[1][bb], o);
        }
    }
    if (lane == 0) {
#pragma unroll
        for (int bb = 0; bb < 4; bb++) {
            const int b = bt * 4 + bb;
            g_part[qs][(size_t)b * KDIM + k0] = a[0][bb];
            g_part[qs][(size_t)b * KDIM + k1] = a[1][bb];
        }
    }
}

// ---------------------------------------------------------------------------
// Kernel 2: PERSISTENT producer/consumer scores pipeline.
// Block-stride over 1024 tiles (b, 128 rows). Producer warp (warp 8, lane 0)
// streams 16-row (32 KB) stages of key into a 6-stage smem ring via
// cp.async.bulk + mbarrier expect_tx. Consumer warps 0-7 each compute 2 rows
// per stage from smem (conflict-free LDS.128), shfl-reduce, exp(tanh(.)),
// store, and per-tile atomicAdd the partial softmax denominator.
// tanh in (-1,1) -> exp bounded -> no max pass needed.
// ---------------------------------------------------------------------------
__global__ void __launch_bounds__(NTHREADS)
scores_pipe(const float* __restrict__ key,
            const float* __restrict__ bias,
            float* __restrict__ out)
{
    extern __shared__ __align__(1024) unsigned char dsmem[];
    const uint32_t sbase = (uint32_t)__cvta_generic_to_shared(dsmem);
    const uint32_t mb    = sbase + SMEM_RING;   // full[s] = mb+16s, empty[s] = mb+16s+8

    const int tid  = threadIdx.x;
    const int warp = tid >> 5;
    const int lane = tid & 31;

    if (tid == 0) {
#pragma unroll
        for (int s = 0; s < STAGES; s++) {
            MBARRIER_INIT(mb + s * 16,     1);           // full: producer arrive+tx
            MBARRIER_INIT(mb + s * 16 + 8, CONS_WARPS);  // empty: 8 consumer arrivals
        }
        asm volatile("fence.proxy.async.shared::cta;" ::: "memory");
    }
    __syncthreads();

    if (warp == CONS_WARPS) {
        // -------- producer --------
        if (lane == 0) {
            int slot = 0, phase = 1;  // phase=1: first STAGES empty-waits pass immediately
            for (int tile = blockIdx.x; tile < NTILES; tile += gridDim.x) {
                const int b     = tile >> 4;
                const int chunk = tile & 15;
                const float* tb = key + ((size_t)b * TDIM + chunk * TILE_ROWS) * KDIM;
#pragma unroll
                for (int st = 0; st < STAGES_PER_TILE; st++) {
                    mbar_wait_relaxed(mb + slot * 16 + 8, (uint32_t)phase);
                    MBARRIER_EXPECT_TX(mb + slot * 16, STAGE_BYTES);
                    bulk_load(sbase + slot * STAGE_BYTES,
                              tb + (size_t)st * STAGE_ROWS * KDIM,
                              STAGE_BYTES, mb + slot * 16);
                    if (++slot == STAGES) { slot = 0; phase ^= 1; }
                }
            }
        }
    } else {
        // -------- consumers (warps 0..7, 2 rows per stage each) --------
        const float bv = bias[0];
        int slot = 0, phase = 0;
        for (int tile = blockIdx.x; tile < NTILES; tile += gridDim.x) {
            const int b     = tile >> 4;
            const int chunk = tile & 15;

            // mids for this batch: sum of 4 q-chunk partials, in registers
            float4 m[4];
#pragma unroll
            for (int j = 0; j < 4; j++) {
                const int idx = lane + 32 * j;
                float4 x0 = reinterpret_cast<const float4*>(g_part[0] + (size_t)b * KDIM)[idx];
                float4 x1 = reinterpret_cast<const float4*>(g_part[1] + (size_t)b * KDIM)[idx];
                float4 x2 = reinterpret_cast<const float4*>(g_part[2] + (size_t)b * KDIM)[idx];
                float4 x3 = reinterpret_cast<const float4*>(g_part[3] + (size_t)b * KDIM)[idx];
                m[j].x = (x0.x + x1.x) + (x2.x + x3.x);
                m[j].y = (x0.y + x1.y) + (x2.y + x3.y);
                m[j].z = (x0.z + x1.z) + (x2.z + x3.z);
                m[j].w = (x0.w + x1.w) + (x2.w + x3.w);
            }

            float wsum = 0.0f;
#pragma unroll
            for (int st = 0; st < STAGES_PER_TILE; st++) {
                mbar_wait(mb + slot * 16, (uint32_t)phase);

                const uint32_t r0 = sbase + slot * STAGE_BYTES + (warp * 2) * (KDIM * 4);
                const uint32_t r1 = r0 + KDIM * 4;

                float a0 = 0.f, a1 = 0.f;
#pragma unroll
                for (int j = 0; j < 4; j++) {
                    const uint32_t off = (uint32_t)(lane + 32 * j) * 16;
                    float4 v0, v1;
                    asm volatile("ld.shared.v4.f32 {%0,%1,%2,%3}, [%4];"
                                 : "=f"(v0.x), "=f"(v0.y), "=f"(v0.z), "=f"(v0.w)
                                 : "r"(r0 + off));
                    asm volatile("ld.shared.v4.f32 {%0,%1,%2,%3}, [%4];"
                                 : "=f"(v1.x), "=f"(v1.y), "=f"(v1.z), "=f"(v1.w)
                                 : "r"(r1 + off));
                    const float4 mv = m[j];
                    a0 += v0.x * mv.x + v0.y * mv.y + v0.z * mv.z + v0.w * mv.w;
                    a1 += v1.x * mv.x + v1.y * mv.y + v1.z * mv.z + v1.w * mv.w;
                }
#pragma unroll
                for (int o = 16; o; o >>= 1) {
                    a0 += __shfl_xor_sync(0xffffffffu, a0, o);
                    a1 += __shfl_xor_sync(0xffffffffu, a1, o);
                }

                if (lane == 0) {
                    const int trow = chunk * TILE_ROWS + st * STAGE_ROWS + warp * 2;
                    float e0 = __expf(tanhf(a0 + bv));
                    float e1 = __expf(tanhf(a1 + bv));
                    float* op = out + (size_t)b * TDIM + trow;
                    op[0] = e0;
                    op[1] = e1;
                    wsum += e0 + e1;
                    MBARRIER_ARRIVE(mb + slot * 16 + 8);  // all lanes done (shfl synced)
                }
                if (++slot == STAGES) { slot = 0; phase ^= 1; }
            }
            if (lane == 0) atomicAdd(&g_sums[b], wsum);
        }
    }
}

// ---------------------------------------------------------------------------
// Kernel 3: normalize in place. 32768 float4s, b = (float4 index) / 512.
// ---------------------------------------------------------------------------
__global__ void norm_kernel(float* __restrict__ out)
{
    const int i = blockIdx.x * blockDim.x + threadIdx.x; // 0..32767
    const int b = i >> 9;  // 512 float4 per batch row (T=2048)
    const float inv = 1.0f / g_sums[b];
    float4* o4 = reinterpret_cast<float4*>(out);
    float4 v = o4[i];
    v.x *= inv; v.y *= inv; v.z *= inv; v.w *= inv;
    o4[i] = v;
}

// ---------------------------------------------------------------------------
// Inputs (metadata order): query [64,512], key [64,2048,512], W [512,512],
// bias [1]. Output: [64,2048] float32.
// ---------------------------------------------------------------------------
extern "C" void kernel_launch(void* const* d_in, const int* in_sizes, int n_in,
                              void* d_out, int out_size)
{
    const float* query = (const float*)d_in[0];
    const float* key   = (const float*)d_in[1];
    const float* W     = (const float*)d_in[2];
    const float* bias  = (const float*)d_in[3];
    float* out = (float*)d_out;

    static int nsm = 0;
    if (nsm == 0) {
        int dev = 0;
        cudaGetDevice(&dev);
        cudaDeviceGetAttribute(&nsm, cudaDevAttrMultiProcessorCount, dev);
        if (nsm <= 0) nsm = 148;
        cudaFuncSetAttribute(scores_pipe,
                             cudaFuncAttributeMaxDynamicSharedMemorySize, SMEM_TOTAL);
    }

    mids_kernel<<<2048, 256>>>(query, W);
    scores_pipe<<<nsm, NTHREADS, SMEM_TOTAL>>>(key, bias, out);
    norm_kernel<<<(BATCH * TDIM / 4) / 256, 256>>>(out);
}

// round 8
// speedup vs baseline: 1.1144x; 1.1144x over previous
#include <cuda_runtime.h>

#define BATCH 64
#define TDIM  2048
#define QDIM  512
#define KDIM  512

// Scratch (no allocations allowed in kernel_launch)
__device__ float g_mids[BATCH * KDIM];
__device__ float g_sums[BATCH];

// ---------------------------------------------------------------------------
// Kernel 1: mids[b,k] = sum_q W[k,q] * query[b,q].
// grid = 1024: kt = x & 63 (64 tiles of 8 k), bt = x >> 6 (16 tiles of 4 b).
// 256 threads = 8 warps; each warp owns ONE k over the FULL q=512 for 4
// batches: 4 coalesced W LDG.128, 16 q LDS.128, 64 FMA4 groups, then a
// single 5-level shfl tree for 4 accumulators (20 shfl total). This cuts
// the reduce-tree instruction count 8x vs the q-split version (the measured
// bottleneck: 2.6M shfl/add warp-instrs out of 5.4M issued).
// Block 0 zeroes g_sums.
// ---------------------------------------------------------------------------
__global__ void __launch_bounds__(256)
mids_kernel(const float* __restrict__ query,
            const float* __restrict__ W)
{
    const int kt = blockIdx.x & 63;   // 0..63 (8 k each)
    const int bt = blockIdx.x >> 6;   // 0..15 (4 b each)

    if (blockIdx.x == 0 && threadIdx.x < BATCH) g_sums[threadIdx.x] = 0.0f;

    __shared__ float q_s[4][QDIM];
    for (int i = threadIdx.x; i < 4 * QDIM; i += blockDim.x) {
        int bb = i >> 9;          // /512
        int q  = i & (QDIM - 1);  // %512
        q_s[bb][q] = query[(size_t)(bt * 4 + bb) * QDIM + q];
    }
    __syncthreads();

    const int warp = threadIdx.x >> 5;
    const int lane = threadIdx.x & 31;
    const int k    = kt * 8 + warp;

    // W row for this k: 4 coalesced float4 per lane (covers q = 4*(lane+32j))
    const float4* w4 = reinterpret_cast<const float4*>(W + (size_t)k * QDIM);
    float4 w[4];
#pragma unroll
    for (int j = 0; j < 4; j++) w[j] = w4[lane + 32 * j];

    float a0 = 0.f, a1 = 0.f, a2 = 0.f, a3 = 0.f;
#pragma unroll
    for (int j = 0; j < 4; j++) {
        const int idx = lane + 32 * j;
        const float4 wv = w[j];
        float4 v0 = reinterpret_cast<const float4*>(q_s[0])[idx];
        float4 v1 = reinterpret_cast<const float4*>(q_s[1])[idx];
        float4 v2 = reinterpret_cast<const float4*>(q_s[2])[idx];
        float4 v3 = reinterpret_cast<const float4*>(q_s[3])[idx];
        a0 += wv.x * v0.x + wv.y * v0.y + wv.z * v0.z + wv.w * v0.w;
        a1 += wv.x * v1.x + wv.y * v1.y + wv.z * v1.z + wv.w * v1.w;
        a2 += wv.x * v2.x + wv.y * v2.y + wv.z * v2.z + wv.w * v2.w;
        a3 += wv.x * v3.x + wv.y * v3.y + wv.z * v3.z + wv.w * v3.w;
    }
#pragma unroll
    for (int o = 16; o; o >>= 1) {
        a0 += __shfl_xor_sync(0xffffffffu, a0, o);
        a1 += __shfl_xor_sync(0xffffffffu, a1, o);
        a2 += __shfl_xor_sync(0xffffffffu, a2, o);
        a3 += __shfl_xor_sync(0xffffffffu, a3, o);
    }
    if (lane == 0) {
        const int b0 = bt * 4;
        g_mids[(size_t)(b0 + 0) * KDIM + k] = a0;
        g_mids[(size_t)(b0 + 1) * KDIM + k] = a1;
        g_mids[(size_t)(b0 + 2) * KDIM + k] = a2;
        g_mids[(size_t)(b0 + 3) * KDIM + k] = a3;
    }
}

// ---------------------------------------------------------------------------
// Kernel 2 (R6 structure — measured best): e[b,t] = exp(tanh(key.mids+bias));
// accumulate per-batch sums. tanh in (-1,1) -> exp bounded -> no max pass.
// grid = 64*32 = 2048 blocks (64 rows each), 256 threads = 8 warps.
// Each warp: 8 rows in ONE burst of 32 independent streaming LDG.128
// (warp-coalesced, 4 lines per LDG), then one interleaved 8-way shfl-reduce.
// ---------------------------------------------------------------------------
__global__ void __launch_bounds__(256)
scores_kernel(const float* __restrict__ key,
              const float* __restrict__ bias,
              float* __restrict__ out)
{
    const int b     = blockIdx.x >> 5;   // 0..63
    const int chunk = blockIdx.x & 31;   // 0..31 (64 rows each)

    __shared__ float ms[KDIM];
    __shared__ float blockSum;
    if (threadIdx.x == 0) blockSum = 0.0f;

    if (threadIdx.x < KDIM / 4) {
        const int i = threadIdx.x;
        reinterpret_cast<float4*>(ms)[i] =
            reinterpret_cast<const float4*>(g_mids + (size_t)b * KDIM)[i];
    }
    __syncthreads();

    const int warp = threadIdx.x >> 5;
    const int lane = threadIdx.x & 31;

    float4 m[4];
#pragma unroll
    for (int j = 0; j < 4; j++)
        m[j] = reinterpret_cast<const float4*>(ms)[lane + 32 * j];

    const int ta = chunk * 64 + warp * 8;
    const float4* kb = reinterpret_cast<const float4*>(
        key + ((size_t)b * TDIM + ta) * KDIM);

    float a0 = 0.f, a1 = 0.f, a2 = 0.f, a3 = 0.f;
    float a4 = 0.f, a5 = 0.f, a6 = 0.f, a7 = 0.f;
#pragma unroll
    for (int j = 0; j < 4; j++) {
        const int idx = lane + 32 * j;
        const float4 mv = m[j];
        float4 v0 = __ldcs(kb + idx + 0 * 128);
        float4 v1 = __ldcs(kb + idx + 1 * 128);
        float4 v2 = __ldcs(kb + idx + 2 * 128);
        float4 v3 = __ldcs(kb + idx + 3 * 128);
        float4 v4 = __ldcs(kb + idx + 4 * 128);
        float4 v5 = __ldcs(kb + idx + 5 * 128);
        float4 v6 = __ldcs(kb + idx + 6 * 128);
        float4 v7 = __ldcs(kb + idx + 7 * 128);
        a0 += v0.x * mv.x + v0.y * mv.y + v0.z * mv.z + v0.w * mv.w;
        a1 += v1.x * mv.x + v1.y * mv.y + v1.z * mv.z + v1.w * mv.w;
        a2 += v2.x * mv.x + v2.y * mv.y + v2.z * mv.z + v2.w * mv.w;
        a3 += v3.x * mv.x + v3.y * mv.y + v3.z * mv.z + v3.w * mv.w;
        a4 += v4.x * mv.x + v4.y * mv.y + v4.z * mv.z + v4.w * mv.w;
        a5 += v5.x * mv.x + v5.y * mv.y + v5.z * mv.z + v5.w * mv.w;
        a6 += v6.x * mv.x + v6.y * mv.y + v6.z * mv.z + v6.w * mv.w;
        a7 += v7.x * mv.x + v7.y * mv.y + v7.z * mv.z + v7.w * mv.w;
    }
#pragma unroll
    for (int o = 16; o; o >>= 1) {
        a0 += __shfl_xor_sync(0xffffffffu, a0, o);
        a1 += __shfl_xor_sync(0xffffffffu, a1, o);
        a2 += __shfl_xor_sync(0xffffffffu, a2, o);
        a3 += __shfl_xor_sync(0xffffffffu, a3, o);
        a4 += __shfl_xor_sync(0xffffffffu, a4, o);
        a5 += __shfl_xor_sync(0xffffffffu, a5, o);
        a6 += __shfl_xor_sync(0xffffffffu, a6, o);
        a7 += __shfl_xor_sync(0xffffffffu, a7, o);
    }

    if (lane == 0) {
        const float bv = bias[0];
        float4 e0, e1;
        e0.x = __expf(tanhf(a0 + bv));
        e0.y = __expf(tanhf(a1 + bv));
        e0.z = __expf(tanhf(a2 + bv));
        e0.w = __expf(tanhf(a3 + bv));
        e1.x = __expf(tanhf(a4 + bv));
        e1.y = __expf(tanhf(a5 + bv));
        e1.z = __expf(tanhf(a6 + bv));
        e1.w = __expf(tanhf(a7 + bv));
        float4* op = reinterpret_cast<float4*>(out + (size_t)b * TDIM + ta);
        op[0] = e0;
        op[1] = e1;
        atomicAdd(&blockSum,
                  ((e0.x + e0.y) + (e0.z + e0.w)) +
                  ((e1.x + e1.y) + (e1.z + e1.w)));
    }
    __syncthreads();
    if (threadIdx.x == 0) atomicAdd(&g_sums[b], blockSum);
}

// ---------------------------------------------------------------------------
// Kernel 3: normalize in place. 32768 float4s, b = (float4 index) / 512.
// ---------------------------------------------------------------------------
__global__ void norm_kernel(float* __restrict__ out)
{
    const int i = blockIdx.x * blockDim.x + threadIdx.x; // 0..32767
    const int b = i >> 9;  // 512 float4 per batch row (T=2048)
    const float inv = 1.0f / g_sums[b];
    float4* o4 = reinterpret_cast<float4*>(out);
    float4 v = o4[i];
    v.x *= inv; v.y *= inv; v.z *= inv; v.w *= inv;
    o4[i] = v;
}

// ---------------------------------------------------------------------------
// Inputs (metadata order): query [64,512], key [64,2048,512], W [512,512],
// bias [1]. Output: [64,2048] float32.
// ---------------------------------------------------------------------------
extern "C" void kernel_launch(void* const* d_in, const int* in_sizes, int n_in,
                              void* d_out, int out_size)
{
    const float* query = (const float*)d_in[0];
    const float* key   = (const float*)d_in[1];
    const float* W     = (const float*)d_in[2];
    const float* bias  = (const float*)d_in[3];
    float* out = (float*)d_out;

    mids_kernel<<<1024, 256>>>(query, W);
    scores_kernel<<<BATCH * 32, 256>>>(key, bias, out);
    norm_kernel<<<(BATCH * TDIM / 4) / 256, 256>>>(out);
}